// round 13
// baseline (speedup 1.0000x reference)
#include <cuda_runtime.h>

#define NIN     64
#define NOUT    64
#define NJ      (NIN * NOUT)       // 4096
#define NKNOTS  10
#define NBASIS  6
#define NRCP    24
#define BATCH_TILE 14
#define THREADS 512

// ---- dynamic shared layout (bytes) ----
#define SFEAT_OFF   0
#define SFEAT_BYTES (7 * BATCH_TILE * NIN * 4)      // 25088 [c][bl][i]
#define SGRID_OFF   (SFEAT_OFF + SFEAT_BYTES)
#define SGRID_BYTES (NKNOTS * 32 * 8)               // 2560
#define SRCP_OFF    (SGRID_OFF + SGRID_BYTES)
#define SRCP_BYTES  (NRCP * 32 * 8)                 // 6144
#define SNRCP_OFF   (SRCP_OFF + SRCP_BYTES)
#define SNRCP_BYTES (NRCP * 32 * 8)                 // 6144
#define YPART_OFF   (SNRCP_OFF + SNRCP_BYTES)
#define YPART_BYTES (8 * NOUT * BATCH_TILE * 4)     // 28672 [ig][o][bl]
#define SMEM_TOTAL  (YPART_OFF + YPART_BYTES)       // 68608

typedef unsigned long long ull;
__device__ __forceinline__ ull pack2(float lo, float hi) {
    ull r; asm("mov.b64 %0, {%1, %2};" : "=l"(r) : "f"(lo), "f"(hi)); return r;
}
#define FMA2(d,a,b,c) asm("fma.rn.f32x2 %0, %1, %2, %3;" : "=l"(d) : "l"(a), "l"(b), "l"(c))
#define MUL2(d,a,b)   asm("mul.rn.f32x2 %0, %1, %2;"     : "=l"(d) : "l"(a), "l"(b))
#define ADD2(d,a,b)   asm("add.rn.f32x2 %0, %1, %2;"     : "=l"(d) : "l"(a), "l"(b))
#define UNPK(lo,hi,p) asm("mov.b64 {%0, %1}, %2;" : "=f"(lo), "=f"(hi) : "l"(p))
#define ABSMASK 0x7FFFFFFF7FFFFFFFULL
#define NEG1X2  0xBF800000BF800000ULL

// L2-resident accumulator + scale table + ticket (zero at load; last block
// resets splacc/ticket each launch -> graph-replay safe).
__device__ __align__(16) float g_splacc[NJ];
__device__ __align__(16) float g_invnorm[NJ];
__device__ unsigned int g_ticket;

struct Smem {
    float (*sfeat)[BATCH_TILE][NIN];   // [c][bl][i]
    ull   (*sgridn01)[32];             // [m][ip]
    ull   (*srcp01)[32];               // [e][ip]
    ull   (*snrcp01)[32];              // [e][ip]
    float (*ypart)[NOUT][BATCH_TILE];  // [ig][o][bl]
};

// ---- P2 core: thread owns (o, ig) -> 8 j; all LDS are warp-uniform broadcasts
template <bool FULL>
__device__ __forceinline__
void p2(const Smem& S, int nbl, int o, int ig,
        const ull cb[4][NBASIS], const ull csp[4], const ull crs[4],
        ull acc[4])
{
    const float* fbase = &S.sfeat[0][0][ig * 8];
    #pragma unroll
    for (int bl = 0; bl < BATCH_TILE; bl++) {
        if (!FULL && bl >= nbl) break;

        // c = 0
        ulonglong2 va = *(const ulonglong2*)(fbase + (0 * BATCH_TILE + bl) * NIN);
        ulonglong2 vb = *(const ulonglong2*)(fbase + (0 * BATCH_TILE + bl) * NIN + 4);
        ull s0, s1, s2, s3;
        MUL2(s0, cb[0][0], va.x);
        MUL2(s1, cb[1][0], va.y);
        MUL2(s2, cb[2][0], vb.x);
        MUL2(s3, cb[3][0], vb.y);
        #pragma unroll
        for (int c = 1; c < NBASIS; c++) {
            va = *(const ulonglong2*)(fbase + (c * BATCH_TILE + bl) * NIN);
            vb = *(const ulonglong2*)(fbase + (c * BATCH_TILE + bl) * NIN + 4);
            FMA2(s0, cb[0][c], va.x, s0);
            FMA2(s1, cb[1][c], va.y, s1);
            FMA2(s2, cb[2][c], vb.x, s2);
            FMA2(s3, cb[3][c], vb.y, s3);
        }
        // |spl| accumulation (packed)
        ull a0 = s0 & ABSMASK, a1 = s1 & ABSMASK;
        ull a2 = s2 & ABSMASK, a3 = s3 & ABSMASK;
        ADD2(acc[0], acc[0], a0);
        ADD2(acc[1], acc[1], a1);
        ADD2(acc[2], acc[2], a2);
        ADD2(acc[3], acc[3], a3);

        // silu features (c = 6)
        va = *(const ulonglong2*)(fbase + (6 * BATCH_TILE + bl) * NIN);
        vb = *(const ulonglong2*)(fbase + (6 * BATCH_TILE + bl) * NIN + 4);
        ull t0, t1, t2, t3;
        MUL2(t0, csp[0], s0); FMA2(t0, crs[0], va.x, t0);
        MUL2(t1, csp[1], s1); FMA2(t1, crs[1], va.y, t1);
        MUL2(t2, csp[2], s2); FMA2(t2, crs[2], vb.x, t2);
        MUL2(t3, csp[3], s3); FMA2(t3, crs[3], vb.y, t3);
        ADD2(t0, t0, t1);
        ADD2(t2, t2, t3);
        ADD2(t0, t0, t2);
        float u, v; UNPK(u, v, t0);
        S.ypart[ig][o][bl] = u + v;        // y[b,o] partial for this ig, done
    }
}

__global__ __launch_bounds__(THREADS, 1)
void kan_fused_kernel(const float* __restrict__ x,
                      const float* __restrict__ c_basis,
                      const float* __restrict__ c_spl,
                      const float* __restrict__ c_res,
                      const float* __restrict__ grid,
                      float* __restrict__ y_out,
                      float* __restrict__ reg_out,
                      int batch, float inv_batch, int nblocks)
{
    extern __shared__ __align__(16) char smem_raw[];
    Smem S;
    S.sfeat    = (float (*)[BATCH_TILE][NIN])(smem_raw + SFEAT_OFF);
    S.sgridn01 = (ull   (*)[32])(smem_raw + SGRID_OFF);
    S.srcp01   = (ull   (*)[32])(smem_raw + SRCP_OFF);
    S.snrcp01  = (ull   (*)[32])(smem_raw + SNRCP_OFF);
    S.ypart    = (float (*)[NOUT][BATCH_TILE])(smem_raw + YPART_OFF);
    __shared__ int s_last;

    const int t    = threadIdx.x;
    const int lane = t & 31;
    const int w    = t >> 5;
    const int o    = lane + 32 * (w & 1);   // 0..63
    const int ig   = w >> 1;                // 0..7, i-block = ig*8 .. ig*8+7
    const int b0   = blockIdx.x * BATCH_TILE;
    const int nbl  = min(BATCH_TILE, batch - b0);

    // ---- 0a: this block's slice of g_invnorm ----
    {
        int span = (NJ + nblocks - 1) / nblocks;
        int j0 = blockIdx.x * span;
        int j1 = min(j0 + span, NJ);
        for (int jj = j0 + t; jj < j1; jj += THREADS) {
            float hi = __ldg(&grid[jj * NKNOTS + NKNOTS - 1]);
            float lo = __ldg(&grid[jj * NKNOTS]);
            g_invnorm[jj] = inv_batch / (hi - lo + 1e-5f);
        }
    }

    // ---- 0b: packed (negated) knots + sign-folded reciprocal tables ----
    for (int p = t; p < NKNOTS * 32; p += THREADS) {
        int ip = p & 31, m = p >> 5;
        int i0 = ip * 2;
        S.sgridn01[m][ip] = pack2(-__ldg(&grid[i0 * NKNOTS + m]),
                                  -__ldg(&grid[(i0 + 1) * NKNOTS + m]));
    }
    for (int p = t; p < NRCP * 32; p += THREADS) {
        int ip = p & 31, e = p >> 5;
        int K = (e < 9) ? 1 : (e < 17) ? 2 : 3;
        int m = (e < 9) ? e : (e < 17) ? e - 9 : e - 17;
        int i0 = ip * 2;
        float r0 = 1.0f / (__ldg(&grid[i0 * NKNOTS + m + K]) - __ldg(&grid[i0 * NKNOTS + m]));
        float r1 = 1.0f / (__ldg(&grid[(i0 + 1) * NKNOTS + m + K]) - __ldg(&grid[(i0 + 1) * NKNOTS + m]));
        S.srcp01[e][ip]  = pack2(r0, r1);
        S.snrcp01[e][ip] = pack2(-r0, -r1);
    }

    // ---- coefficients for this thread's 8 j = (o, ig*8 + 0..7); LDGs issued
    //      here so their latency hides under phase 1 ----
    ull cb[4][NBASIS], csp[4], crs[4];
    #pragma unroll
    for (int k = 0; k < 4; k++) {
        int j0 = o * NIN + (ig * 4 + k) * 2;
        const float4* p4 = (const float4*)(c_basis + (size_t)j0 * NBASIS);
        float4 f0 = __ldg(&p4[0]);
        float4 f1 = __ldg(&p4[1]);
        float4 f2 = __ldg(&p4[2]);
        cb[k][0] = pack2(f0.x, f1.z);
        cb[k][1] = pack2(f0.y, f1.w);
        cb[k][2] = pack2(f0.z, f2.x);
        cb[k][3] = pack2(f0.w, f2.y);
        cb[k][4] = pack2(f1.x, f2.z);
        cb[k][5] = pack2(f1.y, f2.w);
        csp[k] = *(const ull*)&c_spl[j0];
        crs[k] = *(const ull*)&c_res[j0];
    }
    __syncthreads();

    // ---- phase 1: packed basis + silu; thread = (bl, i-pair), 448 active ----
    if (t < BATCH_TILE * 32) {
        const int ip = t & 31;
        const int bl = t >> 5;
        int b = b0 + bl;
        float2 xv = (b < batch) ? *(const float2*)&x[(size_t)b * NIN + ip * 2]
                                : make_float2(0.f, 0.f);
        ull x01 = pack2(xv.x, xv.y);

        ull d01[NKNOTS];
        #pragma unroll
        for (int m = 0; m < NKNOTS; m++) {
            ull nk = S.sgridn01[m][ip];
            ADD2(d01[m], x01, nk);
        }
        ull bs01[9];
        {
            const ull neg1 = NEG1X2;
            float dA, dB; UNPK(dA, dB, d01[0]);
            ull gprev = pack2(dA >= 0.f ? 1.f : 0.f, dB >= 0.f ? 1.f : 0.f);
            #pragma unroll
            for (int m = 0; m < 9; m++) {
                UNPK(dA, dB, d01[m + 1]);
                ull gnext = pack2(dA >= 0.f ? 1.f : 0.f, dB >= 0.f ? 1.f : 0.f);
                FMA2(bs01[m], gnext, neg1, gprev);
                gprev = gnext;
            }
        }
        #pragma unroll
        for (int K = 1; K <= 3; K++) {
            const int off = (K == 1) ? 0 : (K == 2) ? 9 : 17;
            #pragma unroll
            for (int m = 0; m <= 8 - K; m++) {
                ull rl = S.srcp01[off + m][ip];
                ull rr = S.snrcp01[off + m + 1][ip];
                ull left, wgt, wb, nb;
                MUL2(left, d01[m], rl);
                MUL2(wgt, d01[m + K + 1], rr);
                MUL2(wb, wgt, bs01[m + 1]);
                FMA2(nb, left, bs01[m], wb);
                bs01[m] = nb;
            }
        }
        #pragma unroll
        for (int c = 0; c < NBASIS; c++)
            *(ull*)&S.sfeat[c][bl][ip * 2] = bs01[c];
        float sA = xv.x / (1.0f + __expf(-xv.x));
        float sB = xv.y / (1.0f + __expf(-xv.y));
        *(ull*)&S.sfeat[6][bl][ip * 2] = pack2(sA, sB);
    }
    __syncthreads();

    // ---- phase 2: broadcast-LDS packed-FMA; y completes per-thread ----
    ull acc[4] = {0ull, 0ull, 0ull, 0ull};
    if (nbl == BATCH_TILE) p2<true >(S, nbl, o, ig, cb, csp, crs, acc);
    else                   p2<false>(S, nbl, o, ig, cb, csp, crs, acc);

    // ---- |spl| atomics (fire-and-forget; drain overlaps y reduction) ----
    #pragma unroll
    for (int k = 0; k < 4; k++) {
        float a0, a1; UNPK(a0, a1, acc[k]);
        int j = o * NIN + (ig * 4 + k) * 2;
        atomicAdd(&g_splacc[j],     a0);
        atomicAdd(&g_splacc[j + 1], a1);
    }
    __syncthreads();

    // ---- y reduction over ig (8-way) + coalesced store ----
    for (int p = t; p < BATCH_TILE * NOUT; p += THREADS) {
        int bl = p >> 6, oo = p & 63;
        if (bl < nbl) {
            float s = 0.f;
            #pragma unroll
            for (int g = 0; g < 8; g++) s += S.ypart[g][oo][bl];
            y_out[(size_t)(b0 + bl) * NOUT + oo] = s * (1.0f / NIN);
        }
    }

    // ---- last-block-done: finalize spl_reg (pure fp32x4 multiply) ----
    __threadfence();
    __syncthreads();
    if (t == 0) {
        unsigned r = atomicAdd(&g_ticket, 1u);
        s_last = (r == (unsigned)nblocks - 1) ? 1 : 0;
    }
    __syncthreads();
    if (s_last) {
        float4* accv = (float4*)g_splacc;
        float4* invv = (float4*)g_invnorm;
        float4* outv = (float4*)reg_out;
        #pragma unroll
        for (int j4 = t; j4 < NJ / 4; j4 += THREADS) {
            float4 v = __ldcg(&accv[j4]);
            float4 wv = __ldcg(&invv[j4]);
            v.x *= wv.x; v.y *= wv.y; v.z *= wv.z; v.w *= wv.w;
            outv[j4] = v;
            accv[j4] = make_float4(0.f, 0.f, 0.f, 0.f);   // reset for replay
        }
        __threadfence();
        __syncthreads();
        if (t == 0) atomicExch(&g_ticket, 0u);
    }
}

extern "C" void kernel_launch(void* const* d_in, const int* in_sizes, int n_in,
                              void* d_out, int out_size)
{
    const float* x       = (const float*)d_in[0];
    const float* c_basis = (const float*)d_in[1];
    const float* c_spl   = (const float*)d_in[2];
    const float* c_res   = (const float*)d_in[3];
    const float* grid    = (const float*)d_in[4];

    int batch = in_sizes[0] / NIN;

    float* y_out   = (float*)d_out;                 // (batch, 64)
    float* reg_out = y_out + (size_t)batch * NOUT;  // (64, 64)

    cudaFuncSetAttribute(kan_fused_kernel,
                         cudaFuncAttributeMaxDynamicSharedMemorySize, SMEM_TOTAL);

    int nblocks = (batch + BATCH_TILE - 1) / BATCH_TILE;
    kan_fused_kernel<<<nblocks, THREADS, SMEM_TOTAL>>>(x, c_basis, c_spl, c_res, grid,
                                                       y_out, reg_out, batch,
                                                       1.0f / (float)batch, nblocks);
}

// round 14
// speedup vs baseline: 1.9442x; 1.9442x over previous
#include <cuda_runtime.h>

#define NIN     64
#define NOUT    64
#define NJ      (NIN * NOUT)       // 4096
#define NKNOTS  10
#define NBASIS  6
#define NRCP    24
#define BATCH_TILE 14
#define THREADS 512

// ---- dynamic shared layout (bytes) ----
#define SFEAT_OFF   0
#define SFEAT_BYTES (7 * BATCH_TILE * NIN * 4)      // 25088 [c][bl][i]
#define SGRID_OFF   (SFEAT_OFF + SFEAT_BYTES)
#define SGRID_BYTES (NKNOTS * 32 * 8)               // 2560 packed (-kn,-kn')
#define SRCP_OFF    (SGRID_OFF + SGRID_BYTES)
#define SRCP_BYTES  (NRCP * 32 * 8)                 // 6144 packed (+r,+r')
#define SNRCP_OFF   (SRCP_OFF + SRCP_BYTES)
#define SNRCP_BYTES (NRCP * 32 * 8)                 // 6144 packed (-r,-r')
#define SYPART_OFF  (SNRCP_OFF + SNRCP_BYTES)
#define SYPART_BYTES (BATCH_TILE * 16 * 32 * 16)    // 114688 [bl][oq][lane]
#define SPART_OFF   (SYPART_OFF + SYPART_BYTES)
#define SPART_BYTES (BATCH_TILE * 16 * 2 * 16)      // 7168
#define SMEM_TOTAL  (SPART_OFF + SPART_BYTES)       // 161792

typedef unsigned long long ull;
__device__ __forceinline__ ull pack2(float lo, float hi) {
    ull r; asm("mov.b64 %0, {%1, %2};" : "=l"(r) : "f"(lo), "f"(hi)); return r;
}
#define FMA2(d,a,b,c) asm("fma.rn.f32x2 %0, %1, %2, %3;" : "=l"(d) : "l"(a), "l"(b), "l"(c))
#define MUL2(d,a,b)   asm("mul.rn.f32x2 %0, %1, %2;"     : "=l"(d) : "l"(a), "l"(b))
#define ADD2(d,a,b)   asm("add.rn.f32x2 %0, %1, %2;"     : "=l"(d) : "l"(a), "l"(b))
#define UNPK(lo,hi,p) asm("mov.b64 {%0, %1}, %2;" : "=f"(lo), "=f"(hi) : "l"(p))
#define ABSMASK 0x7FFFFFFF7FFFFFFFULL
#define NEG1X2  0xBF800000BF800000ULL

// L2-resident accumulator + scale table + ticket. Zero at module load;
// last block resets splacc/ticket each launch (graph-replay safe).
__device__ __align__(16) float g_splacc[NJ];
__device__ __align__(16) float g_invnorm[NJ];
__device__ unsigned int g_ticket;

struct Smem {
    float  (*sfeat)[BATCH_TILE][NIN];   // [c][bl][i]
    ull    (*sgridn01)[32];             // [m][ip]  (-kn_i, -kn_{i+1})
    ull    (*srcp01)[32];               // [e][ip]  (+r_i, +r_{i+1})
    ull    (*snrcp01)[32];              // [e][ip]  (-r_i, -r_{i+1})
    float4 (*sypart)[16][32];           // [bl][oq][lane]
    float4 (*spart)[2];                 // [item][half]
};

template <bool FULL>
__device__ __forceinline__
void phase2(const Smem& S, int nbl, int lane, int oq,
            const ull cb01[4][NBASIS], const ull csp01[4],
            const ull crs01[4], ull acc01[4])
{
    #pragma unroll
    for (int bl = 0; bl < BATCH_TILE; bl++) {
        if (!FULL && bl >= nbl) break;
        ull f01[7];
        #pragma unroll
        for (int c = 0; c < 7; c++)
            f01[c] = *(const ull*)&S.sfeat[c][bl][lane * 2];

        float4 yp;
        float* ypp = (float*)&yp;
        #pragma unroll
        for (int q = 0; q < 4; q++) {
            ull s01;
            MUL2(s01, cb01[q][0], f01[0]);
            #pragma unroll
            for (int c = 1; c < NBASIS; c++)
                FMA2(s01, cb01[q][c], f01[c], s01);
            ull a01 = s01 & ABSMASK;             // packed |.|
            ADD2(acc01[q], acc01[q], a01);
            ull t01;
            MUL2(t01, csp01[q], s01);
            FMA2(t01, crs01[q], f01[6], t01);
            float t0, t1; UNPK(t0, t1, t01);
            ypp[q] = t0 + t1;
        }
        S.sypart[bl][oq][lane] = yp;    // fire-and-forget
    }
}

__global__ __launch_bounds__(THREADS, 1)
void kan_fused_kernel(const float* __restrict__ x,
                      const float* __restrict__ c_basis,
                      const float* __restrict__ c_spl,
                      const float* __restrict__ c_res,
                      const float* __restrict__ grid,
                      float* __restrict__ y_out,
                      float* __restrict__ reg_out,
                      int batch, float inv_batch, int nblocks)
{
    extern __shared__ __align__(16) char smem_raw[];
    Smem S;
    S.sfeat    = (float  (*)[BATCH_TILE][NIN])(smem_raw + SFEAT_OFF);
    S.sgridn01 = (ull    (*)[32])(smem_raw + SGRID_OFF);
    S.srcp01   = (ull    (*)[32])(smem_raw + SRCP_OFF);
    S.snrcp01  = (ull    (*)[32])(smem_raw + SNRCP_OFF);
    S.sypart   = (float4 (*)[16][32])(smem_raw + SYPART_OFF);
    S.spart    = (float4 (*)[2])(smem_raw + SPART_OFF);
    __shared__ int s_last;

    const int t    = threadIdx.x;
    const int lane = t & 31;
    const int oq   = t >> 5;
    const int b0   = blockIdx.x * BATCH_TILE;
    const int nbl  = min(BATCH_TILE, batch - b0);

    // ---- 0a: this block's slice of g_invnorm (folds inv_batch) ----
    {
        int span = (NJ + nblocks - 1) / nblocks;
        int j0 = blockIdx.x * span;
        int j1 = min(j0 + span, NJ);
        for (int jj = j0 + t; jj < j1; jj += THREADS) {
            float hi = __ldg(&grid[jj * NKNOTS + NKNOTS - 1]);
            float lo = __ldg(&grid[jj * NKNOTS]);
            g_invnorm[jj] = inv_batch / (hi - lo + 1e-5f);
        }
    }

    // ---- 0b: packed (negated) knots + sign-folded reciprocal tables ----
    for (int p = t; p < NKNOTS * 32; p += THREADS) {
        int ip = p & 31, m = p >> 5;
        int i0 = ip * 2;
        S.sgridn01[m][ip] = pack2(-__ldg(&grid[i0 * NKNOTS + m]),
                                  -__ldg(&grid[(i0 + 1) * NKNOTS + m]));
    }
    for (int p = t; p < NRCP * 32; p += THREADS) {
        int ip = p & 31, e = p >> 5;
        int K = (e < 9) ? 1 : (e < 17) ? 2 : 3;
        int m = (e < 9) ? e : (e < 17) ? e - 9 : e - 17;
        int i0 = ip * 2;
        float r0 = 1.0f / (__ldg(&grid[i0 * NKNOTS + m + K]) - __ldg(&grid[i0 * NKNOTS + m]));
        float r1 = 1.0f / (__ldg(&grid[(i0 + 1) * NKNOTS + m + K]) - __ldg(&grid[(i0 + 1) * NKNOTS + m]));
        S.srcp01[e][ip]  = pack2(r0, r1);
        S.snrcp01[e][ip] = pack2(-r0, -r1);
    }
    __syncthreads();

    // ---- phase 1: packed basis + silu; thread = (bl, i-pair), 448 active ----
    if (t < BATCH_TILE * 32) {
        const int ip = t & 31;
        const int bl = t >> 5;
        int b = b0 + bl;
        float2 xv = (b < batch) ? *(const float2*)&x[(size_t)b * NIN + ip * 2]
                                : make_float2(0.f, 0.f);
        ull x01 = pack2(xv.x, xv.y);

        ull d01[NKNOTS];
        #pragma unroll
        for (int m = 0; m < NKNOTS; m++) {
            ull nk = S.sgridn01[m][ip];
            ADD2(d01[m], x01, nk);               // x - kn[m]
        }

        // bases init: bs[m] = ge[m] - ge[m+1] (rolling, from d01 signs)
        ull bs01[9];
        {
            const ull neg1 = NEG1X2;
            float dA, dB; UNPK(dA, dB, d01[0]);
            ull gprev = pack2(dA >= 0.f ? 1.f : 0.f, dB >= 0.f ? 1.f : 0.f);
            #pragma unroll
            for (int m = 0; m < 9; m++) {
                UNPK(dA, dB, d01[m + 1]);
                ull gnext = pack2(dA >= 0.f ? 1.f : 0.f, dB >= 0.f ? 1.f : 0.f);
                FMA2(bs01[m], gnext, neg1, gprev);
                gprev = gnext;
            }
        }

        #pragma unroll
        for (int K = 1; K <= 3; K++) {
            const int off = (K == 1) ? 0 : (K == 2) ? 9 : 17;
            #pragma unroll
            for (int m = 0; m <= 8 - K; m++) {
                ull rl = S.srcp01[off + m][ip];
                ull rr = S.snrcp01[off + m + 1][ip];
                ull left, w, wb, nb;
                MUL2(left, d01[m], rl);
                MUL2(w, d01[m + K + 1], rr);
                MUL2(wb, w, bs01[m + 1]);
                FMA2(nb, left, bs01[m], wb);
                bs01[m] = nb;
            }
        }
        #pragma unroll
        for (int c = 0; c < NBASIS; c++)
            *(ull*)&S.sfeat[c][bl][ip * 2] = bs01[c];
        float sA = xv.x / (1.0f + __expf(-xv.x));
        float sB = xv.y / (1.0f + __expf(-xv.y));
        *(ull*)&S.sfeat[6][bl][ip * 2] = pack2(sA, sB);
    }

    // ---- coefficients loaded after phase 1 (keeps phase-1 regs low) ----
    ull cb01[4][NBASIS], csp01[4], crs01[4];
    #pragma unroll
    for (int q = 0; q < 4; q++) {
        int j0 = (oq * 4 + q) * NIN + lane * 2;
        const float4* p4 = (const float4*)(c_basis + (size_t)j0 * NBASIS);
        float4 f0 = __ldg(&p4[0]);
        float4 f1 = __ldg(&p4[1]);
        float4 f2 = __ldg(&p4[2]);
        cb01[q][0] = pack2(f0.x, f1.z);
        cb01[q][1] = pack2(f0.y, f1.w);
        cb01[q][2] = pack2(f0.z, f2.x);
        cb01[q][3] = pack2(f0.w, f2.y);
        cb01[q][4] = pack2(f1.x, f2.z);
        cb01[q][5] = pack2(f1.y, f2.w);
        csp01[q] = *(const ull*)&c_spl[j0];
        crs01[q] = *(const ull*)&c_res[j0];
    }
    __syncthreads();

    // ---- phase 2: packed-FMA spl / y-partial / packed |spl| ----
    ull acc01[4] = {0ull, 0ull, 0ull, 0ull};
    if (nbl == BATCH_TILE) phase2<true >(S, nbl, lane, oq, cb01, csp01, crs01, acc01);
    else                   phase2<false>(S, nbl, lane, oq, cb01, csp01, crs01, acc01);

    // ---- issue atomics NOW so L2 drain overlaps the epilogue ----
    #pragma unroll
    for (int q = 0; q < 4; q++) {
        float a0, a1; UNPK(a0, a1, acc01[q]);
        int j = (oq * 4 + q) * NIN + lane * 2;
        atomicAdd(&g_splacc[j],     a0);
        atomicAdd(&g_splacc[j + 1], a1);
    }
    __syncthreads();

    // ---- epilogue: reduce lane dim (2 threads per output float4) ----
    {
        int item = t >> 1, half = t & 1;
        int bl = item >> 4, oqr = item & 15;
        if (t < BATCH_TILE * 16 * 2 && bl < nbl) {
            float4 s = make_float4(0.f, 0.f, 0.f, 0.f);
            int base = half * 16;
            #pragma unroll
            for (int k = 0; k < 16; k++) {
                int ls = base + ((k + (t & 15)) & 15);
                float4 v = S.sypart[bl][oqr][ls];
                s.x += v.x; s.y += v.y; s.z += v.z; s.w += v.w;
            }
            S.spart[item][half] = s;
        }
    }
    __syncthreads();
    {
        int item = t;
        int bl = item >> 4, oqr = item & 15;
        if (item < BATCH_TILE * 16 && bl < nbl) {
            float4 a = S.spart[item][0];
            float4 b = S.spart[item][1];
            const float sc = 1.0f / NIN;
            a.x = (a.x + b.x) * sc; a.y = (a.y + b.y) * sc;
            a.z = (a.z + b.z) * sc; a.w = (a.w + b.w) * sc;
            *(float4*)&y_out[(size_t)(b0 + bl) * NOUT + oqr * 4] = a;
        }
    }

    // ---- last-block-done: finalize spl_reg (pure fp32x4 multiply) ----
    __threadfence();
    __syncthreads();
    if (t == 0) {
        unsigned r = atomicAdd(&g_ticket, 1u);
        s_last = (r == (unsigned)nblocks - 1) ? 1 : 0;
    }
    __syncthreads();
    if (s_last) {
        float4* accv = (float4*)g_splacc;
        float4* invv = (float4*)g_invnorm;
        float4* outv = (float4*)reg_out;
        #pragma unroll
        for (int j4 = t; j4 < NJ / 4; j4 += THREADS) {
            float4 v = __ldcg(&accv[j4]);
            float4 w = __ldcg(&invv[j4]);
            v.x *= w.x; v.y *= w.y; v.z *= w.z; v.w *= w.w;
            outv[j4] = v;
            accv[j4] = make_float4(0.f, 0.f, 0.f, 0.f);   // reset for replay
        }
        __threadfence();
        __syncthreads();
        if (t == 0) atomicExch(&g_ticket, 0u);
    }
}

extern "C" void kernel_launch(void* const* d_in, const int* in_sizes, int n_in,
                              void* d_out, int out_size)
{
    const float* x       = (const float*)d_in[0];
    const float* c_basis = (const float*)d_in[1];
    const float* c_spl   = (const float*)d_in[2];
    const float* c_res   = (const float*)d_in[3];
    const float* grid    = (const float*)d_in[4];

    int batch = in_sizes[0] / NIN;

    float* y_out   = (float*)d_out;                 // (batch, 64)
    float* reg_out = y_out + (size_t)batch * NOUT;  // (64, 64)

    cudaFuncSetAttribute(kan_fused_kernel,
                         cudaFuncAttributeMaxDynamicSharedMemorySize, SMEM_TOTAL);

    int nblocks = (batch + BATCH_TILE - 1) / BATCH_TILE;
    kan_fused_kernel<<<nblocks, THREADS, SMEM_TOTAL>>>(x, c_basis, c_spl, c_res, grid,
                                                       y_out, reg_out, batch,
                                                       1.0f / (float)batch, nblocks);
}